// round 14
// baseline (speedup 1.0000x reference)
#include <cuda_runtime.h>
#include <math.h>

#define BB 256
#define SS 4096
#define HH 64
#define GG 192   // 3*H

// Scratch
__device__ float g_buf[(size_t)BB * SS * HH];      // 268 MB  layer activations
__device__ float g_scores[(size_t)BB * 4 * SS];    // 16 MB

__device__ __forceinline__ float sigmoidf_(float x) {
    return 1.0f / (1.0f + __expf(-x));
}
__device__ __forceinline__ float tanhf_(float x) {
    x = fminf(fmaxf(x, -15.0f), 15.0f);
    float e = __expf(2.0f * x);
    return (e - 1.0f) / (e + 1.0f);
}

// R1-proven 4-accumulator dot (seed = bias)
__device__ __forceinline__ float dot64_(const float* __restrict__ w, const float* sv,
                                        float seed) {
    const float4* hv = (const float4*)sv;
    float a0 = seed, a1 = 0.f, a2 = 0.f, a3 = 0.f;
#pragma unroll
    for (int kk = 0; kk < 16; kk++) {
        float4 v = hv[kk];
        a0 = fmaf(w[4 * kk + 0], v.x, a0);
        a1 = fmaf(w[4 * kk + 1], v.y, a1);
        a2 = fmaf(w[4 * kk + 2], v.z, a2);
        a3 = fmaf(w[4 * kk + 3], v.w, a3);
    }
    return (a0 + a1) + (a2 + a3);
}

// ---------------------------------------------------------------------------
// GRU layer, TWO batches per CTA, R1 per-layer structure. 192 threads = one
// gate row each; wi/wh register-resident and shared across both batches; two
// independent dot chains give ILP and amortize the per-step exposure
// (barriers, MUFU, LDS latency) across 2 batches.
// FIRST: x scalar/step -> per-thread broadcast-LDG rings.
// else:  threads 0-63 stage batch0 x, threads 64-127 stage batch1 x.
// ---------------------------------------------------------------------------
template <bool FIRST>
__device__ void gru_layer2(
    const float* __restrict__ wih, const float* __restrict__ whh,
    const float* __restrict__ bih, const float* __restrict__ bhh,
    const float* __restrict__ in0, const float* __restrict__ in1,
    float* __restrict__ out0, float* __restrict__ out1,
    float (*sh)[HH], float (*sx)[2][HH], float (*srz)[128])
{
    const int j = threadIdx.x;
    constexpr int IN = FIRST ? 1 : HH;

    float wi[IN];
    float wh[HH];
#pragma unroll
    for (int k = 0; k < HH; k++) wh[k] = whh[j * HH + k];
#pragma unroll
    for (int k = 0; k < IN; k++) wi[k] = wih[j * IN + k];
    const float bi = bih[j];
    const float bh = bhh[j];

    if (j < HH) { sh[0][j] = 0.0f; sh[1][j] = 0.0f; }

    float xr0[4] = {0.f, 0.f, 0.f, 0.f};     // FIRST: broadcast x rings
    float xr1[4] = {0.f, 0.f, 0.f, 0.f};
    float xreg = 0.0f;                        // !FIRST: staging register
    const float* myin = nullptr;
    int lane = 0, mb = 0;
    if (FIRST) {
#pragma unroll
        for (int i = 0; i < 4; i++) { xr0[i] = in0[i]; xr1[i] = in1[i]; }
    } else if (j < 2 * HH) {
        mb = (j >= HH) ? 1 : 0;
        lane = j - mb * HH;
        myin = mb ? in1 : in0;
        sx[0][mb][lane] = myin[lane];                  // t = 0
        xreg = myin[(size_t)HH + lane];                // t = 1
    }
    __syncthreads();

    for (int t = 0; t < SS; t++) {
        const int cur = t & 1;
        // ---- phase A ----
        float ai0, ai1;
        if (FIRST) {
            ai0 = fmaf(wi[0], xr0[t & 3], bi);
            ai1 = fmaf(wi[0], xr1[t & 3], bi);
            const int tp = t + 4;
            if (tp < SS) { xr0[t & 3] = in0[tp]; xr1[t & 3] = in1[tp]; }
        } else {
            ai0 = dot64_(wi, sx[cur][0], bi);
            ai1 = dot64_(wi, sx[cur][1], bi);
        }
        const float ah0 = dot64_(wh, sh[0], bh);
        const float ah1 = dot64_(wh, sh[1], bh);

        if (j < 128) {
            srz[0][j] = sigmoidf_(ai0 + ah0);
            srz[1][j] = sigmoidf_(ai1 + ah1);
        }
        __syncthreads();

        // ---- phase B ----
        if (j >= 128) {
            const int k = j - 128;
            {
                float r = srz[0][k], z = srz[0][64 + k];
                float n = tanhf_(fmaf(r, ah0, ai0));
                float hn = fmaf(z, sh[0][k] - n, n);
                sh[0][k] = hn;
                out0[(size_t)t * HH + k] = hn;
            }
            {
                float r = srz[1][k], z = srz[1][64 + k];
                float n = tanhf_(fmaf(r, ah1, ai1));
                float hn = fmaf(z, sh[1][k] - n, n);
                sh[1][k] = hn;
                out1[(size_t)t * HH + k] = hn;
            }
        } else if (!FIRST && j < 2 * HH) {
            sx[1 - cur][mb][lane] = xreg;              // stage x_{t+1}
            xreg = (t + 2 < SS) ? myin[(size_t)(t + 2) * HH + lane] : 0.0f;
        }
        __syncthreads();
    }
}

__global__ __launch_bounds__(GG, 1)
void gru_kernel(
    const float* __restrict__ x,
    const float* __restrict__ wih0, const float* __restrict__ whh0,
    const float* __restrict__ bih0, const float* __restrict__ bhh0,
    const float* __restrict__ wih1, const float* __restrict__ whh1,
    const float* __restrict__ bih1, const float* __restrict__ bhh1,
    const float* __restrict__ wih2, const float* __restrict__ whh2,
    const float* __restrict__ bih2, const float* __restrict__ bhh2)
{
    __shared__ __align__(16) float sh[2][HH];
    __shared__ __align__(16) float sx[2][2][HH];     // [buf][batch][k]
    __shared__ float srz[2][128];                    // [batch][row]

    const int b0 = 2 * blockIdx.x, b1 = b0 + 1;
    float* buf0 = g_buf + (size_t)b0 * SS * HH;
    float* buf1 = g_buf + (size_t)b1 * SS * HH;

    gru_layer2<true >(wih0, whh0, bih0, bhh0,
                      x + (size_t)b0 * SS, x + (size_t)b1 * SS,
                      buf0, buf1, sh, sx, srz);
    __syncthreads();
    gru_layer2<false>(wih1, whh1, bih1, bhh1, buf0, buf1, buf0, buf1,
                      sh, sx, srz);
    __syncthreads();
    gru_layer2<false>(wih2, whh2, bih2, bhh2, buf0, buf1, buf0, buf1,
                      sh, sx, srz);
}

// ---------------------------------------------------------------------------
// Attention + head (unchanged; known-good).
// ---------------------------------------------------------------------------
__global__ __launch_bounds__(256)
void attn_kernel(
    const float* __restrict__ in_proj_w, const float* __restrict__ in_proj_b,
    const float* __restrict__ out_proj_w, const float* __restrict__ out_proj_b,
    const float* __restrict__ fc_w, const float* __restrict__ fc_b,
    float* __restrict__ out)
{
    const int b = blockIdx.x;
    const int tid = threadIdx.x;

    __shared__ __align__(16) float shl[HH];
    __shared__ __align__(16) float sq[HH];
    __shared__ __align__(16) float sg[4][HH];
    __shared__ float sc[4];
    __shared__ float sred[4][256];
    __shared__ float sm4[4], sl4[4];
    __shared__ __align__(16) float stile[64][HH];
    __shared__ float sw[4][64];
    __shared__ float su[4][HH];
    __shared__ __align__(16) float sctx[HH];
    __shared__ float sao[HH];

    const float* mybuf = g_buf + (size_t)b * SS * HH;

    if (tid < HH) shl[tid] = mybuf[(size_t)(SS - 1) * HH + tid];
    __syncthreads();

    if (tid < HH) {
        float acc = in_proj_b[tid];
#pragma unroll
        for (int k = 0; k < HH; k++)
            acc = fmaf(in_proj_w[tid * HH + k], shl[k], acc);
        sq[tid] = acc;
    }
    __syncthreads();

    if (tid < HH) {
#pragma unroll
        for (int h = 0; h < 4; h++) {
            float acc = 0.0f;
#pragma unroll
            for (int d = 0; d < 16; d++)
                acc = fmaf(sq[h * 16 + d], in_proj_w[(HH + h * 16 + d) * HH + tid], acc);
            sg[h][tid] = acc * 0.25f;
        }
    }
    if (tid < 4) {
        float acc = 0.0f;
#pragma unroll
        for (int d = 0; d < 16; d++)
            acc = fmaf(sq[tid * 16 + d], in_proj_b[HH + tid * 16 + d], acc);
        sc[tid] = acc * 0.25f;
    }
    __syncthreads();

    float mloc[4] = {-1e30f, -1e30f, -1e30f, -1e30f};
    for (int s = tid; s < SS; s += 256) {
        const float4* ov = (const float4*)(mybuf + (size_t)s * HH);
        float4 o[16];
#pragma unroll
        for (int kk = 0; kk < 16; kk++) o[kk] = ov[kk];
#pragma unroll
        for (int h = 0; h < 4; h++) {
            const float4* gv = (const float4*)sg[h];
            float a0 = sc[h], a1 = 0.f, a2 = 0.f, a3 = 0.f;
#pragma unroll
            for (int kk = 0; kk < 16; kk++) {
                float4 g4 = gv[kk];
                a0 = fmaf(g4.x, o[kk].x, a0);
                a1 = fmaf(g4.y, o[kk].y, a1);
                a2 = fmaf(g4.z, o[kk].z, a2);
                a3 = fmaf(g4.w, o[kk].w, a3);
            }
            float sv = (a0 + a1) + (a2 + a3);
            g_scores[((size_t)(b * 4 + h)) * SS + s] = sv;
            mloc[h] = fmaxf(mloc[h], sv);
        }
    }
#pragma unroll
    for (int h = 0; h < 4; h++) sred[h][tid] = mloc[h];
    __syncthreads();
    if (tid < 4) {
        float m = -1e30f;
        for (int i = 0; i < 256; i++) m = fmaxf(m, sred[tid][i]);
        sm4[tid] = m;
    }
    __syncthreads();

    const int h = tid >> 6;
    const int e = tid & 63;
    const float mh = sm4[h];
    float uacc = 0.0f, lloc = 0.0f;

    for (int tile = 0; tile < SS / 64; tile++) {
        const int s0 = tile * 64;
        {
            float4* st4 = (float4*)stile;
            const float4* gv = (const float4*)(mybuf + (size_t)s0 * HH);
#pragma unroll
            for (int r = 0; r < 4; r++) {
                int idx = tid + r * 256;
                st4[idx] = gv[idx];
            }
        }
        {
            float w = __expf(g_scores[((size_t)(b * 4 + h)) * SS + s0 + e] - mh);
            sw[h][e] = w;
            lloc += w;
        }
        __syncthreads();
#pragma unroll
        for (int sp = 0; sp < 64; sp++)
            uacc = fmaf(sw[h][sp], stile[sp][e], uacc);
        __syncthreads();
    }

    ((float*)sred)[tid] = lloc;
    __syncthreads();
    if (tid < 4) {
        float l = 0.0f;
        for (int i = 0; i < 64; i++) l += ((float*)sred)[tid * 64 + i];
        sl4[tid] = l;
    }
    __syncthreads();

    su[h][e] = uacc / sl4[h];
    __syncthreads();

    if (tid < HH) {
        const int hh = tid >> 4;
        float acc = in_proj_b[128 + tid];
#pragma unroll
        for (int k = 0; k < HH; k++)
            acc = fmaf(in_proj_w[(128 + tid) * HH + k], su[hh][k], acc);
        sctx[tid] = acc;
    }
    __syncthreads();

    if (tid < HH) {
        float acc = out_proj_b[tid];
#pragma unroll
        for (int k = 0; k < HH; k++)
            acc = fmaf(out_proj_w[tid * HH + k], sctx[k], acc);
        sao[tid] = fc_w[tid] * acc;
    }
    __syncthreads();

    if (tid == 0) {
        float lg = fc_b[0];
        for (int i = 0; i < HH; i++) lg += sao[i];
        out[b] = 1.0f / (1.0f + __expf(-lg));
    }
}

// ---------------------------------------------------------------------------
extern "C" void kernel_launch(void* const* d_in, const int* in_sizes, int n_in,
                              void* d_out, int out_size)
{
    const float* x    = (const float*)d_in[0];
    const float* wih0 = (const float*)d_in[1];
    const float* whh0 = (const float*)d_in[2];
    const float* bih0 = (const float*)d_in[3];
    const float* bhh0 = (const float*)d_in[4];
    const float* wih1 = (const float*)d_in[5];
    const float* whh1 = (const float*)d_in[6];
    const float* bih1 = (const float*)d_in[7];
    const float* bhh1 = (const float*)d_in[8];
    const float* wih2 = (const float*)d_in[9];
    const float* whh2 = (const float*)d_in[10];
    const float* bih2 = (const float*)d_in[11];
    const float* bhh2 = (const float*)d_in[12];
    const float* ipw  = (const float*)d_in[13];
    const float* ipb  = (const float*)d_in[14];
    const float* opw  = (const float*)d_in[15];
    const float* opb  = (const float*)d_in[16];
    const float* fcw  = (const float*)d_in[17];
    const float* fcb  = (const float*)d_in[18];

    gru_kernel<<<BB / 2, GG>>>(x, wih0, whh0, bih0, bhh0,   // grid 128, 1 wave
                               wih1, whh1, bih1, bhh1,
                               wih2, whh2, bih2, bhh2);
    attn_kernel<<<BB, 256>>>(ipw, ipb, opw, opb, fcw, fcb, (float*)d_out);
}

// round 15
// speedup vs baseline: 1.3020x; 1.3020x over previous
#include <cuda_runtime.h>
#include <math.h>

#define BB 256
#define SS 4096
#define HH 64
#define GG 192   // 3*H

// Scratch: layer activations, in-place across layers, per-batch contiguous.
__device__ float g_buf[(size_t)BB * SS * HH];      // 268 MB

__device__ __forceinline__ float sigmoidf_(float x) {
    return 1.0f / (1.0f + __expf(-x));
}
__device__ __forceinline__ float tanhf_(float x) {
    x = fminf(fmaxf(x, -15.0f), 15.0f);
    float e = __expf(2.0f * x);
    return (e - 1.0f) / (e + 1.0f);
}

// ---------------------------------------------------------------------------
// GRU layer — EXACT R1 structure (measured 8653.8 us total). One CTA = one
// batch element, 192 threads = one gate row each. Weights in registers, h in
// smem, 2 barriers/step, double-buffered x staging.
// ---------------------------------------------------------------------------
template <bool FIRST>
__device__ void gru_layer(
    const float* __restrict__ wih, const float* __restrict__ whh,
    const float* __restrict__ bih, const float* __restrict__ bhh,
    const float* __restrict__ inp,   // FIRST: x + b*SS (scalar/step); else buf
    float* __restrict__ outp,        // buf (may alias inp; read t+2 < write t)
    float* sh, float (*sx)[HH], float* srz)
{
    const int j = threadIdx.x;
    constexpr int IN = FIRST ? 1 : HH;

    float wi[IN];
    float wh[HH];
#pragma unroll
    for (int k = 0; k < HH; k++) wh[k] = whh[j * HH + k];
#pragma unroll
    for (int k = 0; k < IN; k++) wi[k] = wih[j * IN + k];
    const float bi = bih[j];
    const float bh = bhh[j];

    if (j < HH) sh[j] = 0.0f;
    float xreg = 0.0f;
    if (j < IN) {
        sx[0][j] = inp[j];                 // t = 0
        xreg     = inp[(size_t)IN + j];    // t = 1 (held for next stage)
    }
    __syncthreads();

    for (int t = 0; t < SS; t++) {
        const int cur = t & 1;
        // ---- phase A: input dot + hidden dot ----
        float ai;
        if (FIRST) {
            ai = fmaf(wi[0], sx[cur][0], bi);
        } else {
            const float4* xv = (const float4*)sx[cur];
            float a0 = bi, a1 = 0.f, a2 = 0.f, a3 = 0.f;
#pragma unroll
            for (int kk = 0; kk < 16; kk++) {
                float4 v = xv[kk];
                a0 = fmaf(wi[4 * kk + 0], v.x, a0);
                a1 = fmaf(wi[4 * kk + 1], v.y, a1);
                a2 = fmaf(wi[4 * kk + 2], v.z, a2);
                a3 = fmaf(wi[4 * kk + 3], v.w, a3);
            }
            ai = (a0 + a1) + (a2 + a3);
        }
        float ah;
        {
            const float4* hv = (const float4*)sh;
            float a0 = bh, a1 = 0.f, a2 = 0.f, a3 = 0.f;
#pragma unroll
            for (int kk = 0; kk < 16; kk++) {
                float4 v = hv[kk];
                a0 = fmaf(wh[4 * kk + 0], v.x, a0);
                a1 = fmaf(wh[4 * kk + 1], v.y, a1);
                a2 = fmaf(wh[4 * kk + 2], v.z, a2);
                a3 = fmaf(wh[4 * kk + 3], v.w, a3);
            }
            ah = (a0 + a1) + (a2 + a3);
        }
        if (j < 128) srz[j] = sigmoidf_(ai + ah);   // r rows [0,64), z rows [64,128)
        __syncthreads();

        // ---- phase B ----
        if (j >= 128) {
            const int k = j - 128;
            float r = srz[k];
            float z = srz[64 + k];
            float n = tanhf_(fmaf(r, ah, ai));      // tanh(xn + r*hn), biases inside
            float hp = sh[k];
            float hn = fmaf(z, hp - n, n);          // (1-z)*n + z*h
            sh[k] = hn;
            outp[(size_t)t * HH + k] = hn;
        } else if (j < IN) {
            sx[1 - cur][j] = xreg;                  // stage x_{t+1}
            xreg = (t + 2 < SS) ? inp[(size_t)(t + 2) * IN + j] : 0.0f;
        }
        __syncthreads();
    }
}

__global__ __launch_bounds__(GG)
void gru_kernel(
    const float* __restrict__ x,
    const float* __restrict__ wih0, const float* __restrict__ whh0,
    const float* __restrict__ bih0, const float* __restrict__ bhh0,
    const float* __restrict__ wih1, const float* __restrict__ whh1,
    const float* __restrict__ bih1, const float* __restrict__ bhh1,
    const float* __restrict__ wih2, const float* __restrict__ whh2,
    const float* __restrict__ bih2, const float* __restrict__ bhh2)
{
    __shared__ __align__(16) float sh[HH];
    __shared__ __align__(16) float sx[2][HH];
    __shared__ float srz[128];

    const int b = blockIdx.x;
    float* buf = g_buf + (size_t)b * SS * HH;

    gru_layer<true >(wih0, whh0, bih0, bhh0, x + (size_t)b * SS, buf, sh, sx, srz);
    __syncthreads();
    gru_layer<false>(wih1, whh1, bih1, bhh1, buf, buf, sh, sx, srz);
    __syncthreads();
    gru_layer<false>(wih2, whh2, bih2, bhh2, buf, buf, sh, sx, srz);
}

// ---------------------------------------------------------------------------
// Fused one-pass attention + head (flash-style online softmax).
// One CTA per batch, 256 threads: thread = (h = tid>>6, e|sp = tid&63).
// Per 64-step tile: stage out-tile once in smem (padded stride 65 =>
// conflict-free row AND column access), compute scores from the tile,
// update running max/scale per head, rescale u-accumulator.
// Single pass over g_buf: halves attn DRAM traffic vs the two-pass version.
// ---------------------------------------------------------------------------
__global__ __launch_bounds__(256)
void attn_kernel(
    const float* __restrict__ in_proj_w, const float* __restrict__ in_proj_b,
    const float* __restrict__ out_proj_w, const float* __restrict__ out_proj_b,
    const float* __restrict__ fc_w, const float* __restrict__ fc_b,
    float* __restrict__ out)
{
    const int b = blockIdx.x;
    const int tid = threadIdx.x;
    const int h = tid >> 6;        // head 0..3
    const int e = tid & 63;        // column / step-in-tile index

    __shared__ __align__(16) float shl[HH];
    __shared__ __align__(16) float sq[HH];
    __shared__ __align__(16) float sg[4][HH];
    __shared__ float sc[4];
    __shared__ float stile[64][65];      // padded: 65 % 32 = 1 -> conflict-free both ways
    __shared__ float swv[4][64];         // raw scores, then exp-weights (in place)
    __shared__ float swm[4][2];          // per-head warp-partial maxima
    __shared__ float sm_run[4];          // running max
    __shared__ float sscale[4];          // per-tile rescale factor
    __shared__ float sred[256];
    __shared__ float sl4[4];
    __shared__ float su[4][HH];
    __shared__ __align__(16) float sctx[HH];
    __shared__ float sao[HH];

    const float* mybuf = g_buf + (size_t)b * SS * HH;

    // ---- last hidden state, q = Wq h + bq ----
    if (tid < HH) shl[tid] = mybuf[(size_t)(SS - 1) * HH + tid];
    __syncthreads();
    if (tid < HH) {
        float acc = in_proj_b[tid];
#pragma unroll
        for (int k = 0; k < HH; k++)
            acc = fmaf(in_proj_w[tid * HH + k], shl[k], acc);
        sq[tid] = acc;
    }
    __syncthreads();

    // ---- fold Wk through q: g[h][:] , c[h] (scaled by 1/sqrt(16)=1/4) ----
    if (tid < HH) {
#pragma unroll
        for (int hh = 0; hh < 4; hh++) {
            float acc = 0.0f;
#pragma unroll
            for (int d = 0; d < 16; d++)
                acc = fmaf(sq[hh * 16 + d], in_proj_w[(HH + hh * 16 + d) * HH + tid], acc);
            sg[hh][tid] = acc * 0.25f;
        }
    }
    if (tid < 4) {
        float acc = 0.0f;
#pragma unroll
        for (int d = 0; d < 16; d++)
            acc = fmaf(sq[tid * 16 + d], in_proj_b[HH + tid * 16 + d], acc);
        sc[tid] = acc * 0.25f;
        sm_run[tid] = -1e30f;
    }
    __syncthreads();

    // ---- single pass: tiles of 64 steps ----
    float uacc = 0.0f;     // thread (h, e): running Σ w * out[s][e]
    float lloc = 0.0f;     // thread (h, sp): running Σ w

    for (int tile = 0; tile < SS / 64; tile++) {
        const int s0 = tile * 64;

        // stage tile: 4096 floats, coalesced float4 global reads, scalar STS
        {
            const float4* gv = (const float4*)(mybuf + (size_t)s0 * HH);
#pragma unroll
            for (int r = 0; r < 4; r++) {
                int idx = tid + r * 256;          // float4 index 0..1023
                int row = idx >> 4, c4 = (idx & 15) * 4;
                float4 v = gv[idx];
                stile[row][c4 + 0] = v.x;
                stile[row][c4 + 1] = v.y;
                stile[row][c4 + 2] = v.z;
                stile[row][c4 + 3] = v.w;
            }
        }
        __syncthreads();

        // score for (h, sp=e): s = c[h] + g[h]·stile[sp][:]
        float s;
        {
            float a0 = sc[h], a1 = 0.f, a2 = 0.f, a3 = 0.f;
#pragma unroll
            for (int k = 0; k < HH; k += 4) {
                a0 = fmaf(sg[h][k + 0], stile[e][k + 0], a0);
                a1 = fmaf(sg[h][k + 1], stile[e][k + 1], a1);
                a2 = fmaf(sg[h][k + 2], stile[e][k + 2], a2);
                a3 = fmaf(sg[h][k + 3], stile[e][k + 3], a3);
            }
            s = (a0 + a1) + (a2 + a3);
        }
        swv[h][e] = s;

        // warp max (each warp is a fixed half of one head)
        float wm = s;
#pragma unroll
        for (int off = 16; off > 0; off >>= 1)
            wm = fmaxf(wm, __shfl_xor_sync(0xFFFFFFFFu, wm, off));
        if ((tid & 31) == 0) swm[h][(tid >> 5) & 1] = wm;
        __syncthreads();

        // per-head running max + rescale factor
        if (tid < 4) {
            float mt = fmaxf(swm[tid][0], swm[tid][1]);
            float mo = sm_run[tid];
            float mn = fmaxf(mo, mt);
            sscale[tid] = __expf(mo - mn);
            sm_run[tid] = mn;
        }
        __syncthreads();

        // weights + l update (thread (h, sp))
        const float scl = sscale[h];
        float w = __expf(swv[h][e] - sm_run[h]);
        swv[h][e] = w;
        lloc = lloc * scl + w;
        __syncthreads();

        // u update (thread (h, e)): column read, conflict-free (stride 65)
        {
            float acc = 0.0f;
#pragma unroll
            for (int sp = 0; sp < 64; sp++)
                acc = fmaf(swv[h][sp], stile[sp][e], acc);
            uacc = uacc * scl + acc;
        }
        __syncthreads();
    }

    // ---- reduce l per head ----
    sred[tid] = lloc;
    __syncthreads();
    if (tid < 4) {
        float l = 0.0f;
        for (int i = 0; i < 64; i++) l += sred[tid * 64 + i];
        sl4[tid] = l;
    }
    __syncthreads();

    su[h][e] = uacc / sl4[h];
    __syncthreads();

    // ---- ctx = Wv u + bv ----
    if (tid < HH) {
        const int hh = tid >> 4;
        float acc = in_proj_b[128 + tid];
#pragma unroll
        for (int k = 0; k < HH; k++)
            acc = fmaf(in_proj_w[(128 + tid) * HH + k], su[hh][k], acc);
        sctx[tid] = acc;
    }
    __syncthreads();

    // ---- attn_out = out_proj ctx + b; partial logit ----
    if (tid < HH) {
        float acc = out_proj_b[tid];
#pragma unroll
        for (int k = 0; k < HH; k++)
            acc = fmaf(out_proj_w[tid * HH + k], sctx[k], acc);
        sao[tid] = fc_w[tid] * acc;
    }
    __syncthreads();

    if (tid == 0) {
        float lg = fc_b[0];
        for (int i = 0; i < HH; i++) lg += sao[i];
        out[b] = 1.0f / (1.0f + __expf(-lg));
    }
}

// ---------------------------------------------------------------------------
extern "C" void kernel_launch(void* const* d_in, const int* in_sizes, int n_in,
                              void* d_out, int out_size)
{
    const float* x    = (const float*)d_in[0];
    const float* wih0 = (const float*)d_in[1];
    const float* whh0 = (const float*)d_in[2];
    const float* bih0 = (const float*)d_in[3];
    const float* bhh0 = (const float*)d_in[4];
    const float* wih1 = (const float*)d_in[5];
    const float* whh1 = (const float*)d_in[6];
    const float* bih1 = (const float*)d_in[7];
    const float* bhh1 = (const float*)d_in[8];
    const float* wih2 = (const float*)d_in[9];
    const float* whh2 = (const float*)d_in[10];
    const float* bih2 = (const float*)d_in[11];
    const float* bhh2 = (const float*)d_in[12];
    const float* ipw  = (const float*)d_in[13];
    const float* ipb  = (const float*)d_in[14];
    const float* opw  = (const float*)d_in[15];
    const float* opb  = (const float*)d_in[16];
    const float* fcw  = (const float*)d_in[17];
    const float* fcb  = (const float*)d_in[18];

    gru_kernel<<<BB, GG>>>(x, wih0, whh0, bih0, bhh0,
                           wih1, whh1, bih1, bhh1,
                           wih2, whh2, bih2, bhh2);
    attn_kernel<<<BB, 256>>>(ipw, ipb, opw, opb, fcw, fcb, (float*)d_out);
}

// round 16
// speedup vs baseline: 1.3075x; 1.0042x over previous
#include <cuda_runtime.h>
#include <math.h>

#define BB 256
#define SS 4096
#define HH 64
#define GG 192   // 3*H
#define TS 128   // attn tile steps

// Scratch: layer activations, in-place across layers, per-batch contiguous.
__device__ float g_buf[(size_t)BB * SS * HH];      // 268 MB

__device__ __forceinline__ float sigmoidf_(float x) {
    return 1.0f / (1.0f + __expf(-x));
}
__device__ __forceinline__ float tanhf_(float x) {
    x = fminf(fmaxf(x, -15.0f), 15.0f);
    float e = __expf(2.0f * x);
    return (e - 1.0f) / (e + 1.0f);
}

// ---------------------------------------------------------------------------
// GRU layer — EXACT R1 structure (frozen; measured best). One CTA = one
// batch element, 192 threads = one gate row each. Weights in registers, h in
// smem, 2 barriers/step, double-buffered x staging.
// ---------------------------------------------------------------------------
template <bool FIRST>
__device__ void gru_layer(
    const float* __restrict__ wih, const float* __restrict__ whh,
    const float* __restrict__ bih, const float* __restrict__ bhh,
    const float* __restrict__ inp,   // FIRST: x + b*SS (scalar/step); else buf
    float* __restrict__ outp,        // buf (may alias inp; read t+2 < write t)
    float* sh, float (*sx)[HH], float* srz)
{
    const int j = threadIdx.x;
    constexpr int IN = FIRST ? 1 : HH;

    float wi[IN];
    float wh[HH];
#pragma unroll
    for (int k = 0; k < HH; k++) wh[k] = whh[j * HH + k];
#pragma unroll
    for (int k = 0; k < IN; k++) wi[k] = wih[j * IN + k];
    const float bi = bih[j];
    const float bh = bhh[j];

    if (j < HH) sh[j] = 0.0f;
    float xreg = 0.0f;
    if (j < IN) {
        sx[0][j] = inp[j];                 // t = 0
        xreg     = inp[(size_t)IN + j];    // t = 1 (held for next stage)
    }
    __syncthreads();

    for (int t = 0; t < SS; t++) {
        const int cur = t & 1;
        // ---- phase A: input dot + hidden dot ----
        float ai;
        if (FIRST) {
            ai = fmaf(wi[0], sx[cur][0], bi);
        } else {
            const float4* xv = (const float4*)sx[cur];
            float a0 = bi, a1 = 0.f, a2 = 0.f, a3 = 0.f;
#pragma unroll
            for (int kk = 0; kk < 16; kk++) {
                float4 v = xv[kk];
                a0 = fmaf(wi[4 * kk + 0], v.x, a0);
                a1 = fmaf(wi[4 * kk + 1], v.y, a1);
                a2 = fmaf(wi[4 * kk + 2], v.z, a2);
                a3 = fmaf(wi[4 * kk + 3], v.w, a3);
            }
            ai = (a0 + a1) + (a2 + a3);
        }
        float ah;
        {
            const float4* hv = (const float4*)sh;
            float a0 = bh, a1 = 0.f, a2 = 0.f, a3 = 0.f;
#pragma unroll
            for (int kk = 0; kk < 16; kk++) {
                float4 v = hv[kk];
                a0 = fmaf(wh[4 * kk + 0], v.x, a0);
                a1 = fmaf(wh[4 * kk + 1], v.y, a1);
                a2 = fmaf(wh[4 * kk + 2], v.z, a2);
                a3 = fmaf(wh[4 * kk + 3], v.w, a3);
            }
            ah = (a0 + a1) + (a2 + a3);
        }
        if (j < 128) srz[j] = sigmoidf_(ai + ah);   // r rows [0,64), z rows [64,128)
        __syncthreads();

        // ---- phase B ----
        if (j >= 128) {
            const int k = j - 128;
            float r = srz[k];
            float z = srz[64 + k];
            float n = tanhf_(fmaf(r, ah, ai));      // tanh(xn + r*hn), biases inside
            float hp = sh[k];
            float hn = fmaf(z, hp - n, n);          // (1-z)*n + z*h
            sh[k] = hn;
            outp[(size_t)t * HH + k] = hn;
        } else if (j < IN) {
            sx[1 - cur][j] = xreg;                  // stage x_{t+1}
            xreg = (t + 2 < SS) ? inp[(size_t)(t + 2) * IN + j] : 0.0f;
        }
        __syncthreads();
    }
}

__global__ __launch_bounds__(GG)
void gru_kernel(
    const float* __restrict__ x,
    const float* __restrict__ wih0, const float* __restrict__ whh0,
    const float* __restrict__ bih0, const float* __restrict__ bhh0,
    const float* __restrict__ wih1, const float* __restrict__ whh1,
    const float* __restrict__ bih1, const float* __restrict__ bhh1,
    const float* __restrict__ wih2, const float* __restrict__ whh2,
    const float* __restrict__ bih2, const float* __restrict__ bhh2)
{
    __shared__ __align__(16) float sh[HH];
    __shared__ __align__(16) float sx[2][HH];
    __shared__ float srz[128];

    const int b = blockIdx.x;
    float* buf = g_buf + (size_t)b * SS * HH;

    gru_layer<true >(wih0, whh0, bih0, bhh0, x + (size_t)b * SS, buf, sh, sx, srz);
    __syncthreads();
    gru_layer<false>(wih1, whh1, bih1, bhh1, buf, buf, sh, sx, srz);
    __syncthreads();
    gru_layer<false>(wih2, whh2, bih2, bhh2, buf, buf, sh, sx, srz);
}

// ---------------------------------------------------------------------------
// Fused one-pass attention + head (flash-style online softmax), 128-step
// tiles (32 tiles -> half the barrier/turnover overhead of the 64-step
// version measured at 197us). One CTA per batch, 256 threads:
// thread = (h = tid>>6, e = tid&63); score phase covers sp = e and e+64.
// stile padded to 65 -> conflict-free row AND column access.
// ---------------------------------------------------------------------------
__global__ __launch_bounds__(256)
void attn_kernel(
    const float* __restrict__ in_proj_w, const float* __restrict__ in_proj_b,
    const float* __restrict__ out_proj_w, const float* __restrict__ out_proj_b,
    const float* __restrict__ fc_w, const float* __restrict__ fc_b,
    float* __restrict__ out)
{
    const int b = blockIdx.x;
    const int tid = threadIdx.x;
    const int h = tid >> 6;        // head 0..3
    const int e = tid & 63;        // column index / base step-in-tile

    __shared__ __align__(16) float shl[HH];
    __shared__ __align__(16) float sq[HH];
    __shared__ __align__(16) float sg[4][HH];
    __shared__ float sc[4];
    __shared__ float stile[TS][65];      // 33.3 KB
    __shared__ float swv[4][TS];         // raw scores, then exp-weights
    __shared__ float swm[4][2];          // per-head warp-partial maxima
    __shared__ float sm_run[4];          // running max
    __shared__ float sscale[4];          // per-tile rescale factor
    __shared__ float sred[256];
    __shared__ float sl4[4];
    __shared__ float su[4][HH];
    __shared__ __align__(16) float sctx[HH];
    __shared__ float sao[HH];

    const float* mybuf = g_buf + (size_t)b * SS * HH;

    // ---- last hidden state, q = Wq h + bq ----
    if (tid < HH) shl[tid] = mybuf[(size_t)(SS - 1) * HH + tid];
    __syncthreads();
    if (tid < HH) {
        float acc = in_proj_b[tid];
#pragma unroll
        for (int k = 0; k < HH; k++)
            acc = fmaf(in_proj_w[tid * HH + k], shl[k], acc);
        sq[tid] = acc;
    }
    __syncthreads();

    // ---- fold Wk through q: g[h][:], c[h] (scaled by 1/sqrt(16)=1/4) ----
    if (tid < HH) {
#pragma unroll
        for (int hh = 0; hh < 4; hh++) {
            float acc = 0.0f;
#pragma unroll
            for (int d = 0; d < 16; d++)
                acc = fmaf(sq[hh * 16 + d], in_proj_w[(HH + hh * 16 + d) * HH + tid], acc);
            sg[hh][tid] = acc * 0.25f;
        }
    }
    if (tid < 4) {
        float acc = 0.0f;
#pragma unroll
        for (int d = 0; d < 16; d++)
            acc = fmaf(sq[tid * 16 + d], in_proj_b[HH + tid * 16 + d], acc);
        sc[tid] = acc * 0.25f;
        sm_run[tid] = -1e30f;
    }
    __syncthreads();

    // ---- single pass: tiles of TS steps ----
    float uacc = 0.0f;     // thread (h, e): running Σ w * out[s][e]
    float lloc = 0.0f;     // thread (h, ·): running Σ w over its sp slots

    for (int tile = 0; tile < SS / TS; tile++) {
        const int s0 = tile * TS;

        // stage tile: TS*64 floats = 2048 float4, 8 per thread, coalesced
        {
            const float4* gv = (const float4*)(mybuf + (size_t)s0 * HH);
#pragma unroll
            for (int r = 0; r < (TS * HH / 4) / 256; r++) {
                int idx = tid + r * 256;
                int row = idx >> 4, c4 = (idx & 15) * 4;
                float4 v = gv[idx];
                stile[row][c4 + 0] = v.x;
                stile[row][c4 + 1] = v.y;
                stile[row][c4 + 2] = v.z;
                stile[row][c4 + 3] = v.w;
            }
        }
        __syncthreads();

        // scores for (h, sp = e and e+64): s = c[h] + g[h]·stile[sp][:]
        float s0v, s1v;
#pragma unroll
        for (int half = 0; half < 2; half++) {
            const int sp = e + half * 64;
            float a0 = sc[h], a1 = 0.f, a2 = 0.f, a3 = 0.f;
#pragma unroll
            for (int k = 0; k < HH; k += 4) {
                a0 = fmaf(sg[h][k + 0], stile[sp][k + 0], a0);
                a1 = fmaf(sg[h][k + 1], stile[sp][k + 1], a1);
                a2 = fmaf(sg[h][k + 2], stile[sp][k + 2], a2);
                a3 = fmaf(sg[h][k + 3], stile[sp][k + 3], a3);
            }
            float sv = (a0 + a1) + (a2 + a3);
            swv[h][sp] = sv;
            if (half == 0) s0v = sv; else s1v = sv;
        }

        // warp max over both halves (each warp = fixed half of one head)
        float wm = fmaxf(s0v, s1v);
#pragma unroll
        for (int off = 16; off > 0; off >>= 1)
            wm = fmaxf(wm, __shfl_xor_sync(0xFFFFFFFFu, wm, off));
        if ((tid & 31) == 0) swm[h][(tid >> 5) & 1] = wm;
        __syncthreads();

        // per-head running max + rescale factor
        if (tid < 4) {
            float mt = fmaxf(swm[tid][0], swm[tid][1]);
            float mo = sm_run[tid];
            float mn = fmaxf(mo, mt);
            sscale[tid] = __expf(mo - mn);
            sm_run[tid] = mn;
        }
        __syncthreads();

        // weights + l update
        const float scl = sscale[h];
        const float mh = sm_run[h];
        float w0 = __expf(swv[h][e] - mh);
        float w1 = __expf(swv[h][e + 64] - mh);
        swv[h][e] = w0;
        swv[h][e + 64] = w1;
        lloc = fmaf(lloc, scl, w0 + w1);
        __syncthreads();

        // u update (thread (h, e)): column reads, conflict-free (stride 65)
        {
            float acc = 0.0f;
#pragma unroll
            for (int sp = 0; sp < TS; sp++)
                acc = fmaf(swv[h][sp], stile[sp][e], acc);
            uacc = fmaf(uacc, scl, acc);
        }
        __syncthreads();
    }

    // ---- reduce l per head ----
    sred[tid] = lloc;
    __syncthreads();
    if (tid < 4) {
        float l = 0.0f;
        for (int i = 0; i < 64; i++) l += sred[tid * 64 + i];
        sl4[tid] = l;
    }
    __syncthreads();

    su[h][e] = uacc / sl4[h];
    __syncthreads();

    // ---- ctx = Wv u + bv ----
    if (tid < HH) {
        const int hh = tid >> 4;
        float acc = in_proj_b[128 + tid];
#pragma unroll
        for (int k = 0; k < HH; k++)
            acc = fmaf(in_proj_w[(128 + tid) * HH + k], su[hh][k], acc);
        sctx[tid] = acc;
    }
    __syncthreads();

    // ---- attn_out = out_proj ctx + b; partial logit ----
    if (tid < HH) {
        float acc = out_proj_b[tid];
#pragma unroll
        for (int k = 0; k < HH; k++)
            acc = fmaf(out_proj_w[tid * HH + k], sctx[k], acc);
        sao[tid] = fc_w[tid] * acc;
    }
    __syncthreads();

    if (tid == 0) {
        float lg = fc_b[0];
        for (int i = 0; i < HH; i++) lg += sao[i];
        out[b] = 1.0f / (1.0f + __expf(-lg));
    }
}

// ---------------------------------------------------------------------------
extern "C" void kernel_launch(void* const* d_in, const int* in_sizes, int n_in,
                              void* d_out, int out_size)
{
    const float* x    = (const float*)d_in[0];
    const float* wih0 = (const float*)d_in[1];
    const float* whh0 = (const float*)d_in[2];
    const float* bih0 = (const float*)d_in[3];
    const float* bhh0 = (const float*)d_in[4];
    const float* wih1 = (const float*)d_in[5];
    const float* whh1 = (const float*)d_in[6];
    const float* bih1 = (const float*)d_in[7];
    const float* bhh1 = (const float*)d_in[8];
    const float* wih2 = (const float*)d_in[9];
    const float* whh2 = (const float*)d_in[10];
    const float* bih2 = (const float*)d_in[11];
    const float* bhh2 = (const float*)d_in[12];
    const float* ipw  = (const float*)d_in[13];
    const float* ipb  = (const float*)d_in[14];
    const float* opw  = (const float*)d_in[15];
    const float* opb  = (const float*)d_in[16];
    const float* fcw  = (const float*)d_in[17];
    const float* fcb  = (const float*)d_in[18];

    gru_kernel<<<BB, GG>>>(x, wih0, whh0, bih0, bhh0,
                           wih1, whh1, bih1, bhh1,
                           wih2, whh2, bih2, bhh2);
    attn_kernel<<<BB, 256>>>(ipw, ipb, opw, opb, fcw, fcb, (float*)d_out);
}